// round 7
// baseline (speedup 1.0000x reference)
#include <cuda_runtime.h>
#include <cuda_bf16.h>

// ODE-GRU: B=128, L=2048, I=D=64.
// Round 7: 2-GEMV critical path (M = w_hh@dw2, c = w_hh@db2 precomputed) WITH
// gx computed in-CTA (no scratch GEMM, no per-step DRAM gx reads).
// 1 CTA/batch, 384 threads (12 warps), 2 register-resident packed weight
// rows/thread, 3 barriers/step, all dots via fma.rn.f32x2.
//   Phase A (h):  t1=tanh(h*dw1^T+db1) | G1=h*w_hh^T+b_hh | gx[0:128]
//   Phase B (t1): G2=t1*M^T+c          | f=t1*dw2^T+db2   | gx[128:192]
//   Phase C:      gates (64 lanes), h update, x/dt prefetch commit

#define NB 128
#define NL 2048
#define ND 64
#define NG 192
#define NT 384

typedef unsigned long long u64;

__device__ float g_M[NG * ND];
__device__ float g_c[NG];

__device__ __forceinline__ u64 fma2(u64 a, u64 b, u64 c) {
    u64 d;
    asm("fma.rn.f32x2 %0, %1, %2, %3;" : "=l"(d) : "l"(a), "l"(b), "l"(c));
    return d;
}
__device__ __forceinline__ u64 add2(u64 a, u64 b) {
    u64 d;
    asm("add.rn.f32x2 %0, %1, %2;" : "=l"(d) : "l"(a), "l"(b));
    return d;
}
__device__ __forceinline__ u64 pk(float lo, float hi) {
    u64 r;
    asm("mov.b64 %0, {%1, %2};" : "=l"(r) : "f"(lo), "f"(hi));
    return r;
}

// dot(w_row[64], v[64]) + bias, w pre-packed f32x2.
__device__ __forceinline__ float dot64p(const u64* __restrict__ w,
                                        const float* __restrict__ v,
                                        float bias)
{
    const ulonglong2* __restrict__ v2 = (const ulonglong2*)v;
    u64 a0 = pk(bias, 0.f), a1 = 0ull, a2 = 0ull, a3 = 0ull;
#pragma unroll
    for (int q = 0; q < 8; q++) {
        ulonglong2 p = v2[2*q];
        ulonglong2 r = v2[2*q + 1];
        a0 = fma2(w[4*q+0], p.x, a0);
        a1 = fma2(w[4*q+1], p.y, a1);
        a2 = fma2(w[4*q+2], r.x, a2);
        a3 = fma2(w[4*q+3], r.y, a3);
    }
    u64 s = add2(add2(a0, a1), add2(a2, a3));
    float lo = __uint_as_float((unsigned)s);
    float hi = __uint_as_float((unsigned)(s >> 32));
    return lo + hi;
}

__device__ __forceinline__ float sigmoidf_(float a) {
    return __fdividef(1.f, 1.f + __expf(-a));
}
__device__ __forceinline__ float tanhf_fast(float x) {
    float e = __expf(2.f * x);
    return 1.f - __fdividef(2.f, e + 1.f);
}

// ---------------- setup: M = w_hh @ dw2 (192x64), c = w_hh @ db2 -----------
__global__ __launch_bounds__(64)
void setup_Mc_kernel(const float* __restrict__ w_hh,
                     const float* __restrict__ dw2,
                     const float* __restrict__ db2)
{
    const int k = blockIdx.x;    // 0..191
    const int j = threadIdx.x;   // 0..63
    __shared__ float row[ND];
    row[j] = w_hh[k * ND + j];
    __syncthreads();
    float acc = 0.f;
#pragma unroll 8
    for (int i = 0; i < ND; i++) acc = fmaf(row[i], dw2[i * ND + j], acc);
    g_M[k * ND + j] = acc;
    if (j == 0) {
        float c = 0.f;
        for (int i = 0; i < ND; i++) c = fmaf(row[i], db2[i], c);
        g_c[k] = c;
    }
}

// ---------------- recurrent kernel -----------------------------------------
__global__ __launch_bounds__(NT, 1)
void odegru_kernel(const float* __restrict__ x,
                   const float* __restrict__ tdel,
                   const int*   __restrict__ seq,
                   const float* __restrict__ h0,
                   const float* __restrict__ w_ih,
                   const float* __restrict__ b_ih,
                   const float* __restrict__ b_hh,
                   const float* __restrict__ dw1,
                   const float* __restrict__ db1,
                   const float* __restrict__ dw2,
                   const float* __restrict__ db2,
                   const float* __restrict__ w_hh,
                   float* __restrict__ out)
{
    const int b   = blockIdx.x;
    const int tid = threadIdx.x;

    __shared__ __align__(16) float sh_h[ND];
    __shared__ __align__(16) float sh_t1[ND];
    __shared__ __align__(16) float sh_G1[NG];   // h*w_hh^T + b_hh
    __shared__ __align__(16) float sh_G2[NG];   // t1*M^T + c
    __shared__ __align__(16) float sh_f[ND];    // t1*dw2^T + db2
    __shared__ __align__(16) float sh_gx[NG];   // x_t*w_ih^T + b_ih
    __shared__ __align__(16) float sh_x[2][ND];

    // ---- packed weight rows (<=2 per thread) ----
    u64 wA[32], wB[32];
    float bA, bB;
    const float* pA;
    const float* pB;
    if (tid < 64) {
        pA = dw1 + tid * ND;           bA = db1[tid];
        pB = g_M + tid * ND;           bB = g_c[tid];
    } else if (tid < 192) {
        pA = w_hh + (tid - 64) * ND;   bA = b_hh[tid - 64];
        pB = g_M + tid * ND;           bB = g_c[tid];
    } else if (tid < 256) {
        pA = w_hh + (tid - 64) * ND;   bA = b_hh[tid - 64];
        pB = dw2 + (tid - 192) * ND;   bB = db2[tid - 192];
    } else if (tid < 320) {
        pA = w_ih + (tid - 256) * ND;  bA = b_ih[tid - 256];
        pB = w_ih + (tid - 128) * ND;  bB = b_ih[tid - 128];  // rows 128..191
    } else {
        pA = w_ih + (tid - 256) * ND;  bA = b_ih[tid - 256];
        pB = w_ih + (tid - 256) * ND;  bB = 0.f;              // wB unused
    }
#pragma unroll
    for (int q = 0; q < 32; q++) {
        wA[q] = ((const u64*)pA)[q];
        wB[q] = ((const u64*)pB)[q];
    }

    const int sl = seq[b];
    const float* xb  = x + (size_t)b * NL * ND;
    const float* dtb = tdel + (size_t)b * NL;
    float* outb      = out + (size_t)b * NL * ND;

    if (tid < 64) {
        sh_h[tid]    = h0[tid];
        sh_x[0][tid] = xb[tid];      // t=0 always live (sl >= 1)
    }
    float cdt = (tid < 64) ? dtb[0] : 0.f;
    float fin = 0.f;
    __syncthreads();

    for (int t = 0; t < NL; t++) {
        const int cur = t & 1, nxt = cur ^ 1;
        const int tn  = t + 1;

        // prefetch x/dt for step t+1 (committed in phase C)
        float xr = 0.f, dtn = 0.f;
        if (tid < 64 && tn < NL) {
            xr  = xb[(size_t)tn * ND + tid];
            dtn = dtb[tn];
        }

        // ---- Phase A: t1 | G1 | gx[0:128] ----
        if (tid < 64) {
            sh_t1[tid] = tanhf_fast(dot64p(wA, sh_h, bA));
        } else if (tid < 256) {
            sh_G1[tid - 64] = dot64p(wA, sh_h, bA);
        } else {
            sh_gx[tid - 256] = dot64p(wA, sh_x[cur], bA);
        }
        __syncthreads();

        // ---- Phase B: G2 | f | gx[128:192] ----
        if (tid < 192) {
            sh_G2[tid] = dot64p(wB, sh_t1, bB);
        } else if (tid < 256) {
            sh_f[tid - 192] = dot64p(wB, sh_t1, bB);
        } else if (tid < 320) {
            sh_gx[tid - 128] = dot64p(wB, sh_x[cur], bB);  // rows 128..191
        }
        __syncthreads();

        // ---- Phase C: gates (64 lanes) ----
        if (tid < 64) {
            const int j = tid;
            const float dt = cdt;
            float ho = fmaf(dt, sh_f[j], sh_h[j]);
            float g0 = fmaf(dt, sh_G2[j],       sh_G1[j]);
            float g1 = fmaf(dt, sh_G2[64 + j],  sh_G1[64 + j]);
            float g2 = fmaf(dt, sh_G2[128 + j], sh_G1[128 + j]);
            float r  = sigmoidf_(sh_gx[j]      + g0);
            float z  = sigmoidf_(sh_gx[64 + j] + g1);
            float n  = tanhf_fast(fmaf(r, g2, sh_gx[128 + j]));
            float hn = fmaf(z, ho - n, n);        // (1-z)*n + z*ho
            sh_h[j] = hn;
            outb[(size_t)t * ND + j] = hn;
            if (t == sl - 1) fin = hn;
            sh_x[nxt][j] = (tn < sl) ? xr : 0.f;  // PaddedBatch mask on x
            cdt = (tn < sl) ? dtn : 0.f;          // mask on dt
        }
        __syncthreads();
    }

    // final hidden state -> second output tensor (1, B, D)
    if (tid < 64)
        out[(size_t)NB * NL * ND + (size_t)b * ND + tid] = fin;
}

extern "C" void kernel_launch(void* const* d_in, const int* in_sizes, int n_in,
                              void* d_out, int out_size)
{
    const float* x    = (const float*)d_in[0];
    const float* tdel = (const float*)d_in[1];
    const int*   seq  = (const int*)  d_in[2];
    const float* h0   = (const float*)d_in[3];
    const float* w_ih = (const float*)d_in[4];
    const float* w_hh = (const float*)d_in[5];
    const float* b_ih = (const float*)d_in[6];
    const float* b_hh = (const float*)d_in[7];
    const float* dw1  = (const float*)d_in[8];
    const float* db1  = (const float*)d_in[9];
    const float* dw2  = (const float*)d_in[10];
    const float* db2  = (const float*)d_in[11];

    setup_Mc_kernel<<<NG, 64>>>(w_hh, dw2, db2);
    odegru_kernel<<<NB, NT>>>(x, tdel, seq, h0, w_ih, b_ih, b_hh,
                              dw1, db1, dw2, db2, w_hh, (float*)d_out);
}